// round 1
// baseline (speedup 1.0000x reference)
#include <cuda_runtime.h>
#include <math.h>

// ---------------- problem constants ----------------
#define kB     64
#define kBN    8192        // B*N nodes
#define kE     262144      // edges
#define kH     128
#define kNRBF  64
#define kNBLK  4
#define kNGRID 2048        // filter table resolution
#define kRCUT  6.0f
#define kGAMMA (10.0f / 36.0f)

// ---------------- device scratch (no allocation allowed) ----------------
__device__ float g_h  [kBN * kH];
__device__ float g_hs [kBN * kH];
__device__ float g_agg[kBN * kH];
__device__ float g_t1 [kBN * kH];
__device__ float g_t2 [kBN * kH];
__device__ float g_table[kNBLK * kNGRID * kH];   // w(d) lookup per block
__device__ int   g_deg[kBN];
__device__ int   g_rowptr[kBN + 1];
__device__ int   g_wptr[kBN];

struct __align__(8) SEdge { int s; float t; };
__device__ SEdge g_se[kE];   // edges sorted by dst: (src, grid coordinate)

__device__ __forceinline__ float silu(float x) { return x / (1.0f + expf(-x)); }

// ---------------- small kernels ----------------
__global__ void zero_deg_kernel() {
    int i = blockIdx.x * blockDim.x + threadIdx.x;
    if (i < kBN) g_deg[i] = 0;
}

__global__ void zero_out_kernel(float* out) {
    if (threadIdx.x < kB) out[threadIdx.x] = 0.0f;
}

__global__ void embed_kernel(const int* __restrict__ Z, const float* __restrict__ ew) {
    int n = blockIdx.x;
    int c = threadIdx.x;
    g_h[n * kH + c] = ew[Z[n] * kH + c];
}

__global__ void hist_kernel(const int* __restrict__ ei) {
    int e = blockIdx.x * blockDim.x + threadIdx.x;
    atomicAdd(&g_deg[ei[kE + e]], 1);
}

// exclusive scan of g_deg -> g_rowptr / g_wptr (one CTA, 1024 threads x 8 elems)
__global__ void scan_kernel() {
    __shared__ int part[1024];
    int tid  = threadIdx.x;
    int base = tid * 8;
    int v[8]; int s = 0;
#pragma unroll
    for (int i = 0; i < 8; i++) { v[i] = g_deg[base + i]; s += v[i]; }
    part[tid] = s;
    __syncthreads();
    for (int off = 1; off < 1024; off <<= 1) {
        int t = (tid >= off) ? part[tid - off] : 0;
        __syncthreads();
        part[tid] += t;
        __syncthreads();
    }
    int run = (tid > 0) ? part[tid - 1] : 0;
#pragma unroll
    for (int i = 0; i < 8; i++) {
        g_rowptr[base + i] = run;
        g_wptr[base + i]   = run;
        run += v[i];
    }
    if (tid == 1023) g_rowptr[kBN] = run;
}

// per edge: distance -> grid coord; counting-sort scatter into g_se
__global__ void scatter_kernel(const int* __restrict__ ei, const float* __restrict__ pos) {
    int e = blockIdx.x * blockDim.x + threadIdx.x;
    int s = ei[e];
    int d = ei[kE + e];
    float dx = pos[s * 3 + 0] - pos[d * 3 + 0];
    float dy = pos[s * 3 + 1] - pos[d * 3 + 1];
    float dz = pos[s * 3 + 2] - pos[d * 3 + 2];
    float dist = sqrtf(dx * dx + dy * dy + dz * dz);
    dist = fminf(dist, kRCUT);
    float t = dist * ((float)(kNGRID - 1) / kRCUT);
    int p = atomicAdd(&g_wptr[d], 1);
    SEdge se; se.s = s; se.t = t;
    g_se[p] = se;
}

// ---------------- edge-filter lookup table build ----------------
// grid: (kNGRID/32, kNBLK); 128 threads; dyn smem: W1 + W2 + hidden + rbf
__global__ void table_kernel(const float* __restrict__ w1, const float* __restrict__ b1,
                             const float* __restrict__ w2, const float* __restrict__ b2) {
    extern __shared__ float sm[];
    float* sW1  = sm;                       // 64*128
    float* sW2  = sW1 + kNRBF * kH;         // 128*128
    float* sh   = sW2 + kH * kH;            // 128
    float* srbf = sh + kH;                  // 64
    int blk = blockIdx.y;
    int c   = threadIdx.x;
    const float* W1 = w1 + blk * kNRBF * kH;
    const float* W2 = w2 + blk * kH * kH;
    float bb1 = b1[blk * kH + c];
    float bb2 = b2[blk * kH + c];
    for (int i = c; i < kNRBF * kH; i += kH) sW1[i] = W1[i];
    for (int i = c; i < kH * kH;   i += kH) sW2[i] = W2[i];
    __syncthreads();

    int g0 = blockIdx.x * 32;
    for (int p = 0; p < 32; p++) {
        int g = g0 + p;
        float dd = kRCUT * (float)g / (float)(kNGRID - 1);
        if (c < kNRBF) {
            float ck = kRCUT * (float)c / (float)(kNRBF - 1);
            float u  = dd - ck;
            srbf[c]  = expf(-kGAMMA * u * u);
        }
        __syncthreads();
        float a0 = 0, a1 = 0, a2 = 0, a3 = 0;
#pragma unroll
        for (int k = 0; k < kNRBF; k += 4) {
            a0 += srbf[k + 0] * sW1[(k + 0) * kH + c];
            a1 += srbf[k + 1] * sW1[(k + 1) * kH + c];
            a2 += srbf[k + 2] * sW1[(k + 2) * kH + c];
            a3 += srbf[k + 3] * sW1[(k + 3) * kH + c];
        }
        sh[c] = silu(a0 + a1 + a2 + a3 + bb1);
        __syncthreads();
        float o0 = 0, o1 = 0, o2 = 0, o3 = 0;
#pragma unroll
        for (int j = 0; j < kH; j += 4) {
            o0 += sh[j + 0] * sW2[(j + 0) * kH + c];
            o1 += sh[j + 1] * sW2[(j + 1) * kH + c];
            o2 += sh[j + 2] * sW2[(j + 2) * kH + c];
            o3 += sh[j + 3] * sW2[(j + 3) * kH + c];
        }
        g_table[(blk * kNGRID + g) * kH + c] = o0 + o1 + o2 + o3 + bb2;
        __syncthreads();
    }
}

// ---------------- GEMM: [8192x128] @ [128x128], optional bias / silu ----------------
// MODE 0: plain, 1: bias+silu, 2: bias
// CTA: 256 thr, 64 rows x 128 cols; thread tile 4x8; dyn smem 96KB
template <int MODE>
__global__ void __launch_bounds__(256) gemm_kernel(const float* __restrict__ A,
                                                   const float* __restrict__ W,
                                                   const float* __restrict__ bias,
                                                   float* __restrict__ C) {
    extern __shared__ float sm[];
    float* As = sm;            // 64*128
    float* Bs = sm + 64 * kH;  // 128*128
    int tid = threadIdx.x;
    int m0  = blockIdx.x * 64;

    const float4* A4  = (const float4*)(A + m0 * kH);
    float4*       As4 = (float4*)As;
#pragma unroll
    for (int i = 0; i < 8; i++) As4[tid + i * 256] = A4[tid + i * 256];
    const float4* W4  = (const float4*)W;
    float4*       Bs4 = (float4*)Bs;
#pragma unroll
    for (int i = 0; i < 16; i++) Bs4[tid + i * 256] = W4[tid + i * 256];
    __syncthreads();

    int ty = tid >> 4;   // 0..15 -> 4 rows each
    int tx = tid & 15;   // 0..15 -> 8 cols each
    float acc[4][8];
#pragma unroll
    for (int i = 0; i < 4; i++)
#pragma unroll
        for (int j = 0; j < 8; j++) acc[i][j] = 0.0f;

#pragma unroll 8
    for (int k = 0; k < kH; k++) {
        float av[4];
#pragma unroll
        for (int i = 0; i < 4; i++) av[i] = As[(ty * 4 + i) * kH + k];
        float4 b0 = *(const float4*)&Bs[k * kH + tx * 8];
        float4 b1 = *(const float4*)&Bs[k * kH + tx * 8 + 4];
        float bv[8] = {b0.x, b0.y, b0.z, b0.w, b1.x, b1.y, b1.z, b1.w};
#pragma unroll
        for (int i = 0; i < 4; i++)
#pragma unroll
            for (int j = 0; j < 8; j++) acc[i][j] += av[i] * bv[j];
    }

    float bvreg[8];
    if (MODE >= 1) {
#pragma unroll
        for (int j = 0; j < 8; j++) bvreg[j] = bias[tx * 8 + j];
    }
#pragma unroll
    for (int i = 0; i < 4; i++) {
        int r = m0 + ty * 4 + i;
        float v[8];
#pragma unroll
        for (int j = 0; j < 8; j++) {
            float x = acc[i][j];
            if (MODE >= 1) x += bvreg[j];
            if (MODE == 1) x = silu(x);
            v[j] = x;
        }
        float4* cp = (float4*)&C[r * kH + tx * 8];
        cp[0] = make_float4(v[0], v[1], v[2], v[3]);
        cp[1] = make_float4(v[4], v[5], v[6], v[7]);
    }
}

// ---------------- edge aggregation: one warp per node, float4 per lane ----------------
__global__ void __launch_bounds__(128) agg_kernel(int blk) {
    int warp = threadIdx.x >> 5;
    int lane = threadIdx.x & 31;
    int n    = blockIdx.x * 4 + warp;
    const float4* tab = (const float4*)(g_table + blk * kNGRID * kH);
    const float4* hs4 = (const float4*)g_hs;
    int beg = g_rowptr[n];
    int end = g_rowptr[n + 1];
    float4 acc = make_float4(0.f, 0.f, 0.f, 0.f);
    for (int p = beg; p < end; p++) {
        SEdge e = g_se[p];                       // uniform LDG.64, broadcast
        float t = e.t;
        int   gdx = (int)t;
        if (gdx > kNGRID - 2) gdx = kNGRID - 2;
        float f = t - (float)gdx;
        float4 w0 = tab[gdx * 32 + lane];
        float4 w1 = tab[(gdx + 1) * 32 + lane];
        float4 hv = hs4[e.s * 32 + lane];
        acc.x += (w0.x + (w1.x - w0.x) * f) * hv.x;
        acc.y += (w0.y + (w1.y - w0.y) * f) * hv.y;
        acc.z += (w0.z + (w1.z - w0.z) * f) * hv.z;
        acc.w += (w0.w + (w1.w - w0.w) * f) * hv.w;
    }
    ((float4*)g_agg)[n * 32 + lane] = acc;
}

// ---------------- residual + layernorm: one warp per row ----------------
__global__ void ln_kernel(const float* __restrict__ gg, const float* __restrict__ bb) {
    int warp = threadIdx.x >> 5;
    int lane = threadIdx.x & 31;
    int r    = blockIdx.x * 8 + warp;
    float4 v = ((const float4*)g_h)[r * 32 + lane];
    float4 o = ((const float4*)g_t2)[r * 32 + lane];
    v.x += o.x; v.y += o.y; v.z += o.z; v.w += o.w;
    float s = v.x + v.y + v.z + v.w;
#pragma unroll
    for (int off = 16; off; off >>= 1) s += __shfl_xor_sync(0xffffffffu, s, off);
    float mu = s * (1.0f / 128.0f);
    float d0 = v.x - mu, d1 = v.y - mu, d2 = v.z - mu, d3 = v.w - mu;
    float q = d0 * d0 + d1 * d1 + d2 * d2 + d3 * d3;
#pragma unroll
    for (int off = 16; off; off >>= 1) q += __shfl_xor_sync(0xffffffffu, q, off);
    float rstd = rsqrtf(q * (1.0f / 128.0f) + 1e-5f);
    float4 gv = ((const float4*)gg)[lane];
    float4 bv = ((const float4*)bb)[lane];
    float4 out;
    out.x = d0 * rstd * gv.x + bv.x;
    out.y = d1 * rstd * gv.y + bv.y;
    out.z = d2 * rstd * gv.z + bv.z;
    out.w = d3 * rstd * gv.w + bv.w;
    ((float4*)g_h)[r * 32 + lane] = out;
}

// ---------------- readout: one CTA per node, atomicAdd per graph ----------------
__global__ void readout_kernel(float* __restrict__ out,
                               const float* __restrict__ w1, const float* __restrict__ b1,
                               const float* __restrict__ w2, const float* __restrict__ b2) {
    __shared__ float s[kH];
    __shared__ float red[2];
    int n   = blockIdx.x;
    int tid = threadIdx.x;
    s[tid] = silu(g_h[n * kH + tid]);
    __syncthreads();
    float e = 0.0f;
    if (tid < 64) {
        float x = b1[tid];
#pragma unroll 8
        for (int k = 0; k < kH; k++) x += s[k] * w1[k * 64 + tid];
        e = silu(x) * w2[tid];
    }
#pragma unroll
    for (int off = 16; off; off >>= 1) e += __shfl_down_sync(0xffffffffu, e, off);
    if (tid == 0)  red[0] = e;
    if (tid == 32) red[1] = e;
    __syncthreads();
    if (tid == 0) atomicAdd(&out[n >> 7], red[0] + red[1] + b2[0]);
}

// ---------------- launcher ----------------
extern "C" void kernel_launch(void* const* d_in, const int* in_sizes, int n_in,
                              void* d_out, int out_size) {
    (void)in_sizes; (void)n_in; (void)out_size;
    const int*   Z        = (const int*)  d_in[0];
    const float* pos      = (const float*)d_in[1];
    const int*   ei       = (const int*)  d_in[2];
    const float* embed_w  = (const float*)d_in[3];
    const float* edge_w1  = (const float*)d_in[4];
    const float* edge_b1  = (const float*)d_in[5];
    const float* edge_w2  = (const float*)d_in[6];
    const float* edge_b2  = (const float*)d_in[7];
    const float* lin_in_w = (const float*)d_in[8];
    const float* node_w1  = (const float*)d_in[9];
    const float* node_b1  = (const float*)d_in[10];
    const float* node_w2  = (const float*)d_in[11];
    const float* node_b2  = (const float*)d_in[12];
    const float* ln_g     = (const float*)d_in[13];
    const float* ln_b     = (const float*)d_in[14];
    const float* ro_w1    = (const float*)d_in[15];
    const float* ro_b1    = (const float*)d_in[16];
    const float* ro_w2    = (const float*)d_in[17];
    const float* ro_b2    = (const float*)d_in[18];
    float* out = (float*)d_out;

    float *ph, *phs, *pagg, *pt1, *pt2;
    cudaGetSymbolAddress((void**)&ph,   g_h);
    cudaGetSymbolAddress((void**)&phs,  g_hs);
    cudaGetSymbolAddress((void**)&pagg, g_agg);
    cudaGetSymbolAddress((void**)&pt1,  g_t1);
    cudaGetSymbolAddress((void**)&pt2,  g_t2);

    const int GEMM_SMEM = (64 * kH + kH * kH) * (int)sizeof(float);              // 96 KB
    const int TAB_SMEM  = (kNRBF * kH + kH * kH + kH + kNRBF) * (int)sizeof(float); // ~97 KB
    cudaFuncSetAttribute(gemm_kernel<0>, cudaFuncAttributeMaxDynamicSharedMemorySize, GEMM_SMEM);
    cudaFuncSetAttribute(gemm_kernel<1>, cudaFuncAttributeMaxDynamicSharedMemorySize, GEMM_SMEM);
    cudaFuncSetAttribute(gemm_kernel<2>, cudaFuncAttributeMaxDynamicSharedMemorySize, GEMM_SMEM);
    cudaFuncSetAttribute(table_kernel,   cudaFuncAttributeMaxDynamicSharedMemorySize, TAB_SMEM);

    // ---- per-launch prep (tables + CSR sort); no caching allowed ----
    zero_deg_kernel<<<kBN / 256, 256>>>();
    embed_kernel<<<kBN, kH>>>(Z, embed_w);
    hist_kernel<<<kE / 256, 256>>>(ei);
    scan_kernel<<<1, 1024>>>();
    scatter_kernel<<<kE / 256, 256>>>(ei, pos);
    table_kernel<<<dim3(kNGRID / 32, kNBLK), kH, TAB_SMEM>>>(edge_w1, edge_b1, edge_w2, edge_b2);

    // ---- 4 interaction blocks ----
    for (int b = 0; b < kNBLK; b++) {
        gemm_kernel<0><<<kBN / 64, 256, GEMM_SMEM>>>(ph, lin_in_w + b * kH * kH, nullptr, phs);
        agg_kernel<<<kBN / 4, 128>>>(b);
        gemm_kernel<1><<<kBN / 64, 256, GEMM_SMEM>>>(pagg, node_w1 + b * kH * kH, node_b1 + b * kH, pt1);
        gemm_kernel<2><<<kBN / 64, 256, GEMM_SMEM>>>(pt1, node_w2 + b * kH * kH, node_b2 + b * kH, pt2);
        ln_kernel<<<kBN / 8, 256>>>(ln_g + b * kH, ln_b + b * kH);
    }

    // ---- readout ----
    zero_out_kernel<<<1, 64>>>(out);
    readout_kernel<<<kBN, kH>>>(out, ro_w1, ro_b1, ro_w2, ro_b2);
}

// round 3
// speedup vs baseline: 1.2239x; 1.2239x over previous
#include <cuda_runtime.h>
#include <cuda_fp16.h>
#include <math.h>

// ---------------- problem constants ----------------
#define kB     64
#define kBN    8192        // B*N nodes
#define kE     262144      // edges
#define kH     128
#define kNRBF  64
#define kNBLK  4
#define kNGRID 1024        // filter table resolution
#define kRCUT  6.0f
#define kGAMMA (10.0f / 36.0f)

// ---------------- device scratch ----------------
__device__ float  g_h  [kBN * kH];
__device__ __half g_hsh[kBN * kH];     // h @ lin_in, fp16
__device__ float  g_agg[kBN * kH];
__device__ __half g_tabh[kNBLK * kNGRID * kH];  // w(d) table, fp16
__device__ int    g_deg[kBN];
__device__ int    g_rowptr[kBN + 1];
__device__ int    g_wptr[kBN];

struct __align__(8) SEdge { int s; float t; };
__device__ SEdge g_se[kE];   // edges sorted by dst: (src, grid coord)

__device__ __forceinline__ float silu(float x) { return x / (1.0f + expf(-x)); }

// ---------------- prep kernels ----------------
__global__ void zero_out_kernel(float* out) {
    if (threadIdx.x < kB) out[threadIdx.x] = 0.0f;
}

__global__ void embed_kernel(const int* __restrict__ Z, const float* __restrict__ ew) {
    int n = blockIdx.x;
    int c = threadIdx.x;
    g_h[n * kH + c] = ew[Z[n] * kH + c];
    if (c == 0) g_deg[n] = 0;
}

__global__ void hist_kernel(const int* __restrict__ ei) {
    int e = blockIdx.x * blockDim.x + threadIdx.x;
    atomicAdd(&g_deg[ei[kE + e]], 1);
}

// exclusive scan of g_deg (8192 ints): 256 threads x 32 elems, shfl-based
__global__ void scan_kernel() {
    __shared__ int wsum[8];
    int tid  = threadIdx.x;
    int lane = tid & 31, warp = tid >> 5;
    int base = tid * 32;
    int v[32]; int s = 0;
    const int4* dp = (const int4*)(g_deg + base);
#pragma unroll
    for (int i = 0; i < 8; i++) {
        int4 t = dp[i];
        v[i*4+0] = t.x; v[i*4+1] = t.y; v[i*4+2] = t.z; v[i*4+3] = t.w;
        s += t.x + t.y + t.z + t.w;
    }
    int ps = s;
#pragma unroll
    for (int o = 1; o < 32; o <<= 1) {
        int t = __shfl_up_sync(0xffffffffu, ps, o);
        if (lane >= o) ps += t;
    }
    if (lane == 31) wsum[warp] = ps;
    __syncthreads();
    if (warp == 0 && lane < 8) {
        int w = wsum[lane];
#pragma unroll
        for (int o = 1; o < 8; o <<= 1) {
            int t = __shfl_up_sync(0xffu, w, o);
            if (lane >= o) w += t;
        }
        wsum[lane] = w;
    }
    __syncthreads();
    int run = ps - s + (warp > 0 ? wsum[warp - 1] : 0);  // exclusive prefix
    int4* rp = (int4*)(g_rowptr + base);
    int4* wp = (int4*)(g_wptr + base);
#pragma unroll
    for (int i = 0; i < 8; i++) {
        int4 r;
        r.x = run;            r.y = run + v[i*4+0];
        r.z = r.y + v[i*4+1]; r.w = r.z + v[i*4+2];
        run = r.w + v[i*4+3];
        rp[i] = r; wp[i] = r;
    }
    if (tid == 255) g_rowptr[kBN] = run;
}

// per edge: distance -> grid coord; counting-sort scatter into g_se
__global__ void scatter_kernel(const int* __restrict__ ei, const float* __restrict__ pos) {
    int e = blockIdx.x * blockDim.x + threadIdx.x;
    int s = ei[e];
    int d = ei[kE + e];
    float dx = pos[s * 3 + 0] - pos[d * 3 + 0];
    float dy = pos[s * 3 + 1] - pos[d * 3 + 1];
    float dz = pos[s * 3 + 2] - pos[d * 3 + 2];
    float dist = sqrtf(dx * dx + dy * dy + dz * dz);
    dist = fminf(dist, kRCUT);
    float t = dist * ((float)(kNGRID - 1) / kRCUT);
    int p = atomicAdd(&g_wptr[d], 1);
    SEdge se; se.s = s; se.t = t;
    g_se[p] = se;
}

// ---------------- edge-filter lookup table (fp16) ----------------
// grid (kNGRID/32, kNBLK); 256 threads handle 2 grid points per iter
__global__ void __launch_bounds__(256) table_kernel(
        const float* __restrict__ w1, const float* __restrict__ b1,
        const float* __restrict__ w2, const float* __restrict__ b2) {
    extern __shared__ float sm[];
    float* sW1  = sm;                       // 64*128
    float* sW2  = sW1 + kNRBF * kH;         // 128*128
    float* sh   = sW2 + kH * kH;            // 2*128
    float* srbf = sh + 2 * kH;              // 2*64
    int blk  = blockIdx.y;
    int tid  = threadIdx.x;
    int c    = tid & 127;
    int half = tid >> 7;
    const float* W1 = w1 + blk * kNRBF * kH;
    const float* W2 = w2 + blk * kH * kH;
    float bb1 = b1[blk * kH + c];
    float bb2 = b2[blk * kH + c];
    for (int i = tid; i < kNRBF * kH; i += 256) sW1[i] = W1[i];
    for (int i = tid; i < kH * kH;   i += 256) sW2[i] = W2[i];
    __syncthreads();

    int g0 = blockIdx.x * 32;
    for (int it = 0; it < 16; it++) {
        int g = g0 + it * 2 + half;
        float dd = kRCUT * (float)g / (float)(kNGRID - 1);
        if (c < kNRBF) {
            float ck = kRCUT * (float)c / (float)(kNRBF - 1);
            float u  = dd - ck;
            srbf[half * kNRBF + c] = expf(-kGAMMA * u * u);
        }
        __syncthreads();
        float a0 = 0, a1 = 0, a2 = 0, a3 = 0;
        const float* rb = srbf + half * kNRBF;
#pragma unroll
        for (int k = 0; k < kNRBF; k += 4) {
            a0 += rb[k + 0] * sW1[(k + 0) * kH + c];
            a1 += rb[k + 1] * sW1[(k + 1) * kH + c];
            a2 += rb[k + 2] * sW1[(k + 2) * kH + c];
            a3 += rb[k + 3] * sW1[(k + 3) * kH + c];
        }
        sh[half * kH + c] = silu(a0 + a1 + a2 + a3 + bb1);
        __syncthreads();
        float o0 = 0, o1 = 0, o2 = 0, o3 = 0;
        const float* hh = sh + half * kH;
#pragma unroll
        for (int j = 0; j < kH; j += 4) {
            o0 += hh[j + 0] * sW2[(j + 0) * kH + c];
            o1 += hh[j + 1] * sW2[(j + 1) * kH + c];
            o2 += hh[j + 2] * sW2[(j + 2) * kH + c];
            o3 += hh[j + 3] * sW2[(j + 3) * kH + c];
        }
        g_tabh[(blk * kNGRID + g) * kH + c] = __float2half_rn(o0 + o1 + o2 + o3 + bb2);
        __syncthreads();
    }
}

// ---------------- GEMM hs = h @ lin_in, fp16 output ----------------
// CTA: 256 thr, 64 rows x 128 cols; thread tile 4x8
__global__ void __launch_bounds__(256) gemm_h_kernel(const float* __restrict__ A,
                                                     const float* __restrict__ W,
                                                     __half* __restrict__ C) {
    extern __shared__ float sm[];
    float* As = sm;            // 64*128
    float* Bs = sm + 64 * kH;  // 128*128
    int tid = threadIdx.x;
    int m0  = blockIdx.x * 64;

    const float4* A4  = (const float4*)(A + m0 * kH);
    float4*       As4 = (float4*)As;
#pragma unroll
    for (int i = 0; i < 8; i++) As4[tid + i * 256] = A4[tid + i * 256];
    const float4* W4  = (const float4*)W;
    float4*       Bs4 = (float4*)Bs;
#pragma unroll
    for (int i = 0; i < 16; i++) Bs4[tid + i * 256] = W4[tid + i * 256];
    __syncthreads();

    int ty = tid >> 4;
    int tx = tid & 15;
    float acc[4][8];
#pragma unroll
    for (int i = 0; i < 4; i++)
#pragma unroll
        for (int j = 0; j < 8; j++) acc[i][j] = 0.0f;

#pragma unroll 8
    for (int k = 0; k < kH; k++) {
        float av[4];
#pragma unroll
        for (int i = 0; i < 4; i++) av[i] = As[(ty * 4 + i) * kH + k];
        float4 b0 = *(const float4*)&Bs[k * kH + tx * 8];
        float4 b1 = *(const float4*)&Bs[k * kH + tx * 8 + 4];
        float bv[8] = {b0.x, b0.y, b0.z, b0.w, b1.x, b1.y, b1.z, b1.w};
#pragma unroll
        for (int i = 0; i < 4; i++)
#pragma unroll
            for (int j = 0; j < 8; j++) acc[i][j] += av[i] * bv[j];
    }

#pragma unroll
    for (int i = 0; i < 4; i++) {
        int r = m0 + ty * 4 + i;
        __half2 p0 = __floats2half2_rn(acc[i][0], acc[i][1]);
        __half2 p1 = __floats2half2_rn(acc[i][2], acc[i][3]);
        __half2 p2 = __floats2half2_rn(acc[i][4], acc[i][5]);
        __half2 p3 = __floats2half2_rn(acc[i][6], acc[i][7]);
        uint4 u;
        u.x = *reinterpret_cast<unsigned*>(&p0);
        u.y = *reinterpret_cast<unsigned*>(&p1);
        u.z = *reinterpret_cast<unsigned*>(&p2);
        u.w = *reinterpret_cast<unsigned*>(&p3);
        *reinterpret_cast<uint4*>(&C[r * kH + tx * 8]) = u;
    }
}

// ---------------- edge aggregation: warp/node, fp16 table + fp16 hs ----------------
__global__ void __launch_bounds__(128) agg_kernel(int blk) {
    int warp = threadIdx.x >> 5;
    int lane = threadIdx.x & 31;
    int n    = blockIdx.x * 4 + warp;
    const uint2* tab = (const uint2*)(g_tabh + blk * kNGRID * kH);  // 32 uint2/row
    const uint2* hs  = (const uint2*)g_hsh;
    int beg = g_rowptr[n];
    int end = g_rowptr[n + 1];
    float4 acc = make_float4(0.f, 0.f, 0.f, 0.f);
    for (int p = beg; p < end; p++) {
        SEdge e = g_se[p];
        float t = e.t;
        int   gdx = (int)t;
        if (gdx > kNGRID - 2) gdx = kNGRID - 2;
        float f = t - (float)gdx;
        uint2 u0 = tab[gdx * 32 + lane];
        uint2 u1 = tab[(gdx + 1) * 32 + lane];
        uint2 uh = hs[e.s * 32 + lane];
        float2 w0a = __half22float2(*reinterpret_cast<__half2*>(&u0.x));
        float2 w0b = __half22float2(*reinterpret_cast<__half2*>(&u0.y));
        float2 w1a = __half22float2(*reinterpret_cast<__half2*>(&u1.x));
        float2 w1b = __half22float2(*reinterpret_cast<__half2*>(&u1.y));
        float2 hva = __half22float2(*reinterpret_cast<__half2*>(&uh.x));
        float2 hvb = __half22float2(*reinterpret_cast<__half2*>(&uh.y));
        acc.x += (w0a.x + (w1a.x - w0a.x) * f) * hva.x;
        acc.y += (w0a.y + (w1a.y - w0a.y) * f) * hva.y;
        acc.z += (w0b.x + (w1b.x - w0b.x) * f) * hvb.x;
        acc.w += (w0b.y + (w1b.y - w0b.y) * f) * hvb.y;
    }
    ((float4*)g_agg)[n * 32 + lane] = acc;
}

// ---------------- fused node MLP + residual + LayerNorm ----------------
// t1 = silu(agg@W1+b1) kept in smem; h = LN(h + t1@W2+b2)
__global__ void __launch_bounds__(256) node_fused_kernel(
        const float* __restrict__ W1, const float* __restrict__ b1,
        const float* __restrict__ W2, const float* __restrict__ b2,
        const float* __restrict__ lng, const float* __restrict__ lnb) {
    extern __shared__ float sm[];
    float* As = sm;            // 64*128  (agg tile, then t1)
    float* Bs = sm + 64 * kH;  // 128*128 (W1, then W2)
    int tid = threadIdx.x;
    int m0  = blockIdx.x * 64;
    int ty  = tid >> 4;
    int tx  = tid & 15;

    const float4* A4  = (const float4*)(g_agg + m0 * kH);
    float4*       As4 = (float4*)As;
#pragma unroll
    for (int i = 0; i < 8; i++) As4[tid + i * 256] = A4[tid + i * 256];
    const float4* W14 = (const float4*)W1;
    float4*       Bs4 = (float4*)Bs;
#pragma unroll
    for (int i = 0; i < 16; i++) Bs4[tid + i * 256] = W14[tid + i * 256];
    __syncthreads();

    float acc[4][8];
#pragma unroll
    for (int i = 0; i < 4; i++)
#pragma unroll
        for (int j = 0; j < 8; j++) acc[i][j] = 0.0f;
#pragma unroll 8
    for (int k = 0; k < kH; k++) {
        float av[4];
#pragma unroll
        for (int i = 0; i < 4; i++) av[i] = As[(ty * 4 + i) * kH + k];
        float4 b0v = *(const float4*)&Bs[k * kH + tx * 8];
        float4 b1v = *(const float4*)&Bs[k * kH + tx * 8 + 4];
        float bv[8] = {b0v.x, b0v.y, b0v.z, b0v.w, b1v.x, b1v.y, b1v.z, b1v.w};
#pragma unroll
        for (int i = 0; i < 4; i++)
#pragma unroll
            for (int j = 0; j < 8; j++) acc[i][j] += av[i] * bv[j];
    }
    __syncthreads();   // all reads of As/Bs done

    // t1 = silu(acc + b1) -> As ; load W2 -> Bs
    {
        float4 bb0 = *(const float4*)&b1[tx * 8];
        float4 bb1 = *(const float4*)&b1[tx * 8 + 4];
        float bb[8] = {bb0.x, bb0.y, bb0.z, bb0.w, bb1.x, bb1.y, bb1.z, bb1.w};
#pragma unroll
        for (int i = 0; i < 4; i++) {
            int r = ty * 4 + i;
#pragma unroll
            for (int j = 0; j < 8; j++)
                As[r * kH + tx * 8 + j] = silu(acc[i][j] + bb[j]);
        }
        const float4* W24 = (const float4*)W2;
#pragma unroll
        for (int i = 0; i < 16; i++) Bs4[tid + i * 256] = W24[tid + i * 256];
    }
    __syncthreads();

#pragma unroll
    for (int i = 0; i < 4; i++)
#pragma unroll
        for (int j = 0; j < 8; j++) acc[i][j] = 0.0f;
#pragma unroll 8
    for (int k = 0; k < kH; k++) {
        float av[4];
#pragma unroll
        for (int i = 0; i < 4; i++) av[i] = As[(ty * 4 + i) * kH + k];
        float4 b0v = *(const float4*)&Bs[k * kH + tx * 8];
        float4 b1v = *(const float4*)&Bs[k * kH + tx * 8 + 4];
        float bv[8] = {b0v.x, b0v.y, b0v.z, b0v.w, b1v.x, b1v.y, b1v.z, b1v.w};
#pragma unroll
        for (int i = 0; i < 4; i++)
#pragma unroll
            for (int j = 0; j < 8; j++) acc[i][j] += av[i] * bv[j];
    }

    // epilogue: + b2 + residual h, LayerNorm across the 16 tx-threads per row
    float4 bb0 = *(const float4*)&b2[tx * 8];
    float4 bb1 = *(const float4*)&b2[tx * 8 + 4];
    float bb[8] = {bb0.x, bb0.y, bb0.z, bb0.w, bb1.x, bb1.y, bb1.z, bb1.w};
    float4 gg0 = *(const float4*)&lng[tx * 8];
    float4 gg1 = *(const float4*)&lng[tx * 8 + 4];
    float gg[8] = {gg0.x, gg0.y, gg0.z, gg0.w, gg1.x, gg1.y, gg1.z, gg1.w};
    float4 lb0 = *(const float4*)&lnb[tx * 8];
    float4 lb1 = *(const float4*)&lnb[tx * 8 + 4];
    float lb[8] = {lb0.x, lb0.y, lb0.z, lb0.w, lb1.x, lb1.y, lb1.z, lb1.w};

#pragma unroll
    for (int i = 0; i < 4; i++) {
        int r = m0 + ty * 4 + i;
        float4 h0 = *(const float4*)&g_h[r * kH + tx * 8];
        float4 h1 = *(const float4*)&g_h[r * kH + tx * 8 + 4];
        float hv[8] = {h0.x, h0.y, h0.z, h0.w, h1.x, h1.y, h1.z, h1.w};
        float v[8];
        float s = 0.0f;
#pragma unroll
        for (int j = 0; j < 8; j++) { v[j] = acc[i][j] + bb[j] + hv[j]; s += v[j]; }
#pragma unroll
        for (int o = 1; o < 16; o <<= 1) s += __shfl_xor_sync(0xffffffffu, s, o);
        float mu = s * (1.0f / 128.0f);
        float q = 0.0f;
        float d[8];
#pragma unroll
        for (int j = 0; j < 8; j++) { d[j] = v[j] - mu; q += d[j] * d[j]; }
#pragma unroll
        for (int o = 1; o < 16; o <<= 1) q += __shfl_xor_sync(0xffffffffu, q, o);
        float rstd = rsqrtf(q * (1.0f / 128.0f) + 1e-5f);
        float w[8];
#pragma unroll
        for (int j = 0; j < 8; j++) w[j] = d[j] * rstd * gg[j] + lb[j];
        *(float4*)&g_h[r * kH + tx * 8]     = make_float4(w[0], w[1], w[2], w[3]);
        *(float4*)&g_h[r * kH + tx * 8 + 4] = make_float4(w[4], w[5], w[6], w[7]);
    }
}

// ---------------- readout ----------------
__global__ void readout_kernel(float* __restrict__ out,
                               const float* __restrict__ w1, const float* __restrict__ b1,
                               const float* __restrict__ w2, const float* __restrict__ b2) {
    __shared__ float s[kH];
    __shared__ float red[2];
    int n   = blockIdx.x;
    int tid = threadIdx.x;
    s[tid] = silu(g_h[n * kH + tid]);
    __syncthreads();
    float e = 0.0f;
    if (tid < 64) {
        float x = b1[tid];
#pragma unroll 8
        for (int k = 0; k < kH; k++) x += s[k] * w1[k * 64 + tid];
        e = silu(x) * w2[tid];
    }
#pragma unroll
    for (int off = 16; off; off >>= 1) e += __shfl_down_sync(0xffffffffu, e, off);
    if (tid == 0)  red[0] = e;
    if (tid == 32) red[1] = e;
    __syncthreads();
    if (tid == 0) atomicAdd(&out[n >> 7], red[0] + red[1] + b2[0]);
}

// ---------------- launcher ----------------
extern "C" void kernel_launch(void* const* d_in, const int* in_sizes, int n_in,
                              void* d_out, int out_size) {
    (void)in_sizes; (void)n_in; (void)out_size;
    const int*   Z        = (const int*)  d_in[0];
    const float* pos      = (const float*)d_in[1];
    const int*   ei       = (const int*)  d_in[2];
    const float* embed_w  = (const float*)d_in[3];
    const float* edge_w1  = (const float*)d_in[4];
    const float* edge_b1  = (const float*)d_in[5];
    const float* edge_w2  = (const float*)d_in[6];
    const float* edge_b2  = (const float*)d_in[7];
    const float* lin_in_w = (const float*)d_in[8];
    const float* node_w1  = (const float*)d_in[9];
    const float* node_b1  = (const float*)d_in[10];
    const float* node_w2  = (const float*)d_in[11];
    const float* node_b2  = (const float*)d_in[12];
    const float* ln_g     = (const float*)d_in[13];
    const float* ln_b     = (const float*)d_in[14];
    const float* ro_w1    = (const float*)d_in[15];
    const float* ro_b1    = (const float*)d_in[16];
    const float* ro_w2    = (const float*)d_in[17];
    const float* ro_b2    = (const float*)d_in[18];
    float* out = (float*)d_out;

    float *ph;
    __half *phs;
    cudaGetSymbolAddress((void**)&ph,  g_h);
    cudaGetSymbolAddress((void**)&phs, g_hsh);

    const int GEMM_SMEM = (64 * kH + kH * kH) * (int)sizeof(float);                   // 96 KB
    const int TAB_SMEM  = (kNRBF * kH + kH * kH + 2 * kH + 2 * kNRBF) * (int)sizeof(float);
    cudaFuncSetAttribute(gemm_h_kernel,     cudaFuncAttributeMaxDynamicSharedMemorySize, GEMM_SMEM);
    cudaFuncSetAttribute(node_fused_kernel, cudaFuncAttributeMaxDynamicSharedMemorySize, GEMM_SMEM);
    cudaFuncSetAttribute(table_kernel,      cudaFuncAttributeMaxDynamicSharedMemorySize, TAB_SMEM);

    // ---- prep: embedding, CSR sort, filter tables ----
    embed_kernel<<<kBN, kH>>>(Z, embed_w);
    hist_kernel<<<kE / 256, 256>>>(ei);
    scan_kernel<<<1, 256>>>();
    scatter_kernel<<<kE / 256, 256>>>(ei, pos);
    table_kernel<<<dim3(kNGRID / 32, kNBLK), 256, TAB_SMEM>>>(edge_w1, edge_b1, edge_w2, edge_b2);

    // ---- 4 interaction blocks ----
    for (int b = 0; b < kNBLK; b++) {
        gemm_h_kernel<<<kBN / 64, 256, GEMM_SMEM>>>(ph, lin_in_w + b * kH * kH, phs);
        agg_kernel<<<kBN / 4, 128>>>(b);
        node_fused_kernel<<<kBN / 64, 256, GEMM_SMEM>>>(
            node_w1 + b * kH * kH, node_b1 + b * kH,
            node_w2 + b * kH * kH, node_b2 + b * kH,
            ln_g + b * kH, ln_b + b * kH);
    }

    // ---- readout ----
    zero_out_kernel<<<1, 64>>>(out);
    readout_kernel<<<kBN, kH>>>(out, ro_w1, ro_b1, ro_w2, ro_b2);
}

// round 4
// speedup vs baseline: 1.2740x; 1.0409x over previous
#include <cuda_runtime.h>
#include <cuda_fp16.h>
#include <math.h>

// ---------------- problem constants ----------------
#define kB     64
#define kBN    8192        // B*N nodes
#define kE     262144      // edges
#define kH     128
#define kNRBF  64
#define kNBLK  4
#define kNGRID 1024        // filter table resolution
#define kCAP   128         // max edges per node bucket (lambda=32)
#define kRCUT  6.0f
#define kGAMMA (10.0f / 36.0f)

// ---------------- device scratch ----------------
__device__ float  g_h  [kBN * kH];
__device__ __half g_hsh[kBN * kH];               // h @ lin_in, fp16
__device__ float  g_agg[kBN * kH];
__device__ __half g_tabh[kNBLK * kNGRID * kH];   // w(d) table, fp16
__device__ int    g_deg[kBN];

struct __align__(8) SEdge { int s; float t; };
__device__ SEdge g_se[kBN * kCAP];   // bucketed edges per dst node

__device__ __forceinline__ float silu(float x) { return x / (1.0f + expf(-x)); }

// ---------------- prep kernels ----------------
__global__ void zero_out_kernel(float* out) {
    if (threadIdx.x < kB) out[threadIdx.x] = 0.0f;
}

__global__ void embed_kernel(const int* __restrict__ Z, const float* __restrict__ ew) {
    int n = blockIdx.x;
    int c = threadIdx.x;
    g_h[n * kH + c] = ew[Z[n] * kH + c];
    if (c == 0) g_deg[n] = 0;
}

// direct bucket scatter: 2 edges per thread, batched loads for ILP
__global__ void scatter_kernel(const int* __restrict__ ei, const float* __restrict__ pos) {
    int t2 = blockIdx.x * blockDim.x + threadIdx.x;
    int2 sp = *(const int2*)(ei + t2 * 2);        // src pair
    int2 dp = *(const int2*)(ei + kE + t2 * 2);   // dst pair
    float s0x = pos[sp.x * 3 + 0], s0y = pos[sp.x * 3 + 1], s0z = pos[sp.x * 3 + 2];
    float d0x = pos[dp.x * 3 + 0], d0y = pos[dp.x * 3 + 1], d0z = pos[dp.x * 3 + 2];
    float s1x = pos[sp.y * 3 + 0], s1y = pos[sp.y * 3 + 1], s1z = pos[sp.y * 3 + 2];
    float d1x = pos[dp.y * 3 + 0], d1y = pos[dp.y * 3 + 1], d1z = pos[dp.y * 3 + 2];
    float ax = s0x - d0x, ay = s0y - d0y, az = s0z - d0z;
    float bx = s1x - d1x, by = s1y - d1y, bz = s1z - d1z;
    float r0 = fminf(sqrtf(ax * ax + ay * ay + az * az), kRCUT);
    float r1 = fminf(sqrtf(bx * bx + by * by + bz * bz), kRCUT);
    const float sc = (float)(kNGRID - 1) / kRCUT;
    int p0 = atomicAdd(&g_deg[dp.x], 1);
    int p1 = atomicAdd(&g_deg[dp.y], 1);
    SEdge e0; e0.s = sp.x; e0.t = r0 * sc;
    SEdge e1; e1.s = sp.y; e1.t = r1 * sc;
    if (p0 < kCAP) g_se[dp.x * kCAP + p0] = e0;
    if (p1 < kCAP) g_se[dp.y * kCAP + p1] = e1;
}

// ---------------- edge-filter lookup table (fp16) ----------------
__global__ void __launch_bounds__(256) table_kernel(
        const float* __restrict__ w1, const float* __restrict__ b1,
        const float* __restrict__ w2, const float* __restrict__ b2) {
    extern __shared__ float sm[];
    float* sW1  = sm;                       // 64*128
    float* sW2  = sW1 + kNRBF * kH;         // 128*128
    float* sh   = sW2 + kH * kH;            // 2*128
    float* srbf = sh + 2 * kH;              // 2*64
    int blk  = blockIdx.y;
    int tid  = threadIdx.x;
    int c    = tid & 127;
    int half = tid >> 7;
    const float* W1 = w1 + blk * kNRBF * kH;
    const float* W2 = w2 + blk * kH * kH;
    float bb1 = b1[blk * kH + c];
    float bb2 = b2[blk * kH + c];
    for (int i = tid; i < kNRBF * kH; i += 256) sW1[i] = W1[i];
    for (int i = tid; i < kH * kH;   i += 256) sW2[i] = W2[i];
    __syncthreads();

    int g0 = blockIdx.x * 32;
    for (int it = 0; it < 16; it++) {
        int g = g0 + it * 2 + half;
        float dd = kRCUT * (float)g / (float)(kNGRID - 1);
        if (c < kNRBF) {
            float ck = kRCUT * (float)c / (float)(kNRBF - 1);
            float u  = dd - ck;
            srbf[half * kNRBF + c] = expf(-kGAMMA * u * u);
        }
        __syncthreads();
        float a0 = 0, a1 = 0, a2 = 0, a3 = 0;
        const float* rb = srbf + half * kNRBF;
#pragma unroll
        for (int k = 0; k < kNRBF; k += 4) {
            a0 += rb[k + 0] * sW1[(k + 0) * kH + c];
            a1 += rb[k + 1] * sW1[(k + 1) * kH + c];
            a2 += rb[k + 2] * sW1[(k + 2) * kH + c];
            a3 += rb[k + 3] * sW1[(k + 3) * kH + c];
        }
        sh[half * kH + c] = silu(a0 + a1 + a2 + a3 + bb1);
        __syncthreads();
        float o0 = 0, o1 = 0, o2 = 0, o3 = 0;
        const float* hh = sh + half * kH;
#pragma unroll
        for (int j = 0; j < kH; j += 4) {
            o0 += hh[j + 0] * sW2[(j + 0) * kH + c];
            o1 += hh[j + 1] * sW2[(j + 1) * kH + c];
            o2 += hh[j + 2] * sW2[(j + 2) * kH + c];
            o3 += hh[j + 3] * sW2[(j + 3) * kH + c];
        }
        g_tabh[(blk * kNGRID + g) * kH + c] = __float2half_rn(o0 + o1 + o2 + o3 + bb2);
        __syncthreads();
    }
}

// ---------------- initial GEMM hs = h @ lin_in[0], fp16 out ----------------
__global__ void __launch_bounds__(256) gemm_h_kernel(const float* __restrict__ A,
                                                     const float* __restrict__ W,
                                                     __half* __restrict__ C) {
    extern __shared__ float sm[];
    float* As = sm;            // 64*128
    float* Bs = sm + 64 * kH;  // 128*128
    int tid = threadIdx.x;
    int m0  = blockIdx.x * 64;

    const float4* A4  = (const float4*)(A + m0 * kH);
    float4*       As4 = (float4*)As;
#pragma unroll
    for (int i = 0; i < 8; i++) As4[tid + i * 256] = A4[tid + i * 256];
    const float4* W4  = (const float4*)W;
    float4*       Bs4 = (float4*)Bs;
#pragma unroll
    for (int i = 0; i < 16; i++) Bs4[tid + i * 256] = W4[tid + i * 256];
    __syncthreads();

    int ty = tid >> 4;
    int tx = tid & 15;
    float acc[4][8];
#pragma unroll
    for (int i = 0; i < 4; i++)
#pragma unroll
        for (int j = 0; j < 8; j++) acc[i][j] = 0.0f;

#pragma unroll 8
    for (int k = 0; k < kH; k++) {
        float av[4];
#pragma unroll
        for (int i = 0; i < 4; i++) av[i] = As[(ty * 4 + i) * kH + k];
        float4 b0 = *(const float4*)&Bs[k * kH + tx * 8];
        float4 b1 = *(const float4*)&Bs[k * kH + tx * 8 + 4];
        float bv[8] = {b0.x, b0.y, b0.z, b0.w, b1.x, b1.y, b1.z, b1.w};
#pragma unroll
        for (int i = 0; i < 4; i++)
#pragma unroll
            for (int j = 0; j < 8; j++) acc[i][j] += av[i] * bv[j];
    }

#pragma unroll
    for (int i = 0; i < 4; i++) {
        int r = m0 + ty * 4 + i;
        __half2 p0 = __floats2half2_rn(acc[i][0], acc[i][1]);
        __half2 p1 = __floats2half2_rn(acc[i][2], acc[i][3]);
        __half2 p2 = __floats2half2_rn(acc[i][4], acc[i][5]);
        __half2 p3 = __floats2half2_rn(acc[i][6], acc[i][7]);
        uint4 u;
        u.x = *reinterpret_cast<unsigned*>(&p0);
        u.y = *reinterpret_cast<unsigned*>(&p1);
        u.z = *reinterpret_cast<unsigned*>(&p2);
        u.w = *reinterpret_cast<unsigned*>(&p3);
        *reinterpret_cast<uint4*>(&C[r * kH + tx * 8]) = u;
    }
}

// ---------------- edge aggregation: warp/node, fp16 table + fp16 hs ----------------
__global__ void __launch_bounds__(128) agg_kernel(int blk) {
    int warp = threadIdx.x >> 5;
    int lane = threadIdx.x & 31;
    int n    = blockIdx.x * 4 + warp;
    const uint2* tab = (const uint2*)(g_tabh + blk * kNGRID * kH);
    const uint2* hs  = (const uint2*)g_hsh;
    int len  = g_deg[n];
    if (len > kCAP) len = kCAP;
    const SEdge* row = g_se + n * kCAP;
    float4 acc = make_float4(0.f, 0.f, 0.f, 0.f);
    for (int p = 0; p < len; p++) {
        SEdge e = row[p];
        float t = e.t;
        int   gdx = (int)t;
        if (gdx > kNGRID - 2) gdx = kNGRID - 2;
        float f = t - (float)gdx;
        uint2 u0 = tab[gdx * 32 + lane];
        uint2 u1 = tab[(gdx + 1) * 32 + lane];
        uint2 uh = hs[e.s * 32 + lane];
        float2 w0a = __half22float2(*reinterpret_cast<__half2*>(&u0.x));
        float2 w0b = __half22float2(*reinterpret_cast<__half2*>(&u0.y));
        float2 w1a = __half22float2(*reinterpret_cast<__half2*>(&u1.x));
        float2 w1b = __half22float2(*reinterpret_cast<__half2*>(&u1.y));
        float2 hva = __half22float2(*reinterpret_cast<__half2*>(&uh.x));
        float2 hvb = __half22float2(*reinterpret_cast<__half2*>(&uh.y));
        acc.x += (w0a.x + (w1a.x - w0a.x) * f) * hva.x;
        acc.y += (w0a.y + (w1a.y - w0a.y) * f) * hva.y;
        acc.z += (w0b.x + (w1b.x - w0b.x) * f) * hvb.x;
        acc.w += (w0b.y + (w1b.y - w0b.y) * f) * hvb.y;
    }
    ((float4*)g_agg)[n * 32 + lane] = acc;
}

// ---------------- fused node MLP + residual + LayerNorm + next lin_in ----------------
// stage1: t1 = silu(agg@W1+b1) (smem); stage2: h = LN(h + t1@W2+b2);
// stage3 (if !LAST): hs = h @ Wnext -> fp16
template <int LAST>
__global__ void __launch_bounds__(256) node_fused_kernel(
        const float* __restrict__ W1, const float* __restrict__ b1,
        const float* __restrict__ W2, const float* __restrict__ b2,
        const float* __restrict__ lng, const float* __restrict__ lnb,
        const float* __restrict__ Wnext) {
    extern __shared__ float sm[];
    float* As = sm;            // 64*128  (agg -> t1 -> h)
    float* Bs = sm + 64 * kH;  // 128*128 (W1 -> W2 -> Wnext)
    int tid = threadIdx.x;
    int m0  = blockIdx.x * 64;
    int ty  = tid >> 4;
    int tx  = tid & 15;

    const float4* A4  = (const float4*)(g_agg + m0 * kH);
    float4*       As4 = (float4*)As;
#pragma unroll
    for (int i = 0; i < 8; i++) As4[tid + i * 256] = A4[tid + i * 256];
    const float4* W14 = (const float4*)W1;
    float4*       Bs4 = (float4*)Bs;
#pragma unroll
    for (int i = 0; i < 16; i++) Bs4[tid + i * 256] = W14[tid + i * 256];
    __syncthreads();

    float acc[4][8];
#pragma unroll
    for (int i = 0; i < 4; i++)
#pragma unroll
        for (int j = 0; j < 8; j++) acc[i][j] = 0.0f;
#pragma unroll 8
    for (int k = 0; k < kH; k++) {
        float av[4];
#pragma unroll
        for (int i = 0; i < 4; i++) av[i] = As[(ty * 4 + i) * kH + k];
        float4 b0v = *(const float4*)&Bs[k * kH + tx * 8];
        float4 b1v = *(const float4*)&Bs[k * kH + tx * 8 + 4];
        float bv[8] = {b0v.x, b0v.y, b0v.z, b0v.w, b1v.x, b1v.y, b1v.z, b1v.w};
#pragma unroll
        for (int i = 0; i < 4; i++)
#pragma unroll
            for (int j = 0; j < 8; j++) acc[i][j] += av[i] * bv[j];
    }
    __syncthreads();

    // t1 = silu(acc + b1) -> As ; W2 -> Bs
    {
        float4 bb0 = *(const float4*)&b1[tx * 8];
        float4 bb1 = *(const float4*)&b1[tx * 8 + 4];
        float bb[8] = {bb0.x, bb0.y, bb0.z, bb0.w, bb1.x, bb1.y, bb1.z, bb1.w};
#pragma unroll
        for (int i = 0; i < 4; i++) {
            int r = ty * 4 + i;
#pragma unroll
            for (int j = 0; j < 8; j++)
                As[r * kH + tx * 8 + j] = silu(acc[i][j] + bb[j]);
        }
        const float4* W24 = (const float4*)W2;
#pragma unroll
        for (int i = 0; i < 16; i++) Bs4[tid + i * 256] = W24[tid + i * 256];
    }
    __syncthreads();

#pragma unroll
    for (int i = 0; i < 4; i++)
#pragma unroll
        for (int j = 0; j < 8; j++) acc[i][j] = 0.0f;
#pragma unroll 8
    for (int k = 0; k < kH; k++) {
        float av[4];
#pragma unroll
        for (int i = 0; i < 4; i++) av[i] = As[(ty * 4 + i) * kH + k];
        float4 b0v = *(const float4*)&Bs[k * kH + tx * 8];
        float4 b1v = *(const float4*)&Bs[k * kH + tx * 8 + 4];
        float bv[8] = {b0v.x, b0v.y, b0v.z, b0v.w, b1v.x, b1v.y, b1v.z, b1v.w};
#pragma unroll
        for (int i = 0; i < 4; i++)
#pragma unroll
            for (int j = 0; j < 8; j++) acc[i][j] += av[i] * bv[j];
    }
    __syncthreads();   // stage-2 reads of As/Bs done; safe to overwrite

    // epilogue: + b2 + residual, LayerNorm across 16 tx-threads per row
    float4 bb0 = *(const float4*)&b2[tx * 8];
    float4 bb1 = *(const float4*)&b2[tx * 8 + 4];
    float bb[8] = {bb0.x, bb0.y, bb0.z, bb0.w, bb1.x, bb1.y, bb1.z, bb1.w};
    float4 gg0 = *(const float4*)&lng[tx * 8];
    float4 gg1 = *(const float4*)&lng[tx * 8 + 4];
    float gg[8] = {gg0.x, gg0.y, gg0.z, gg0.w, gg1.x, gg1.y, gg1.z, gg1.w};
    float4 lb0 = *(const float4*)&lnb[tx * 8];
    float4 lb1 = *(const float4*)&lnb[tx * 8 + 4];
    float lb[8] = {lb0.x, lb0.y, lb0.z, lb0.w, lb1.x, lb1.y, lb1.z, lb1.w};

#pragma unroll
    for (int i = 0; i < 4; i++) {
        int r = m0 + ty * 4 + i;
        float4 h0 = *(const float4*)&g_h[r * kH + tx * 8];
        float4 h1 = *(const float4*)&g_h[r * kH + tx * 8 + 4];
        float hv[8] = {h0.x, h0.y, h0.z, h0.w, h1.x, h1.y, h1.z, h1.w};
        float v[8];
        float s = 0.0f;
#pragma unroll
        for (int j = 0; j < 8; j++) { v[j] = acc[i][j] + bb[j] + hv[j]; s += v[j]; }
#pragma unroll
        for (int o = 1; o < 16; o <<= 1) s += __shfl_xor_sync(0xffffffffu, s, o);
        float mu = s * (1.0f / 128.0f);
        float q = 0.0f;
        float d[8];
#pragma unroll
        for (int j = 0; j < 8; j++) { d[j] = v[j] - mu; q += d[j] * d[j]; }
#pragma unroll
        for (int o = 1; o < 16; o <<= 1) q += __shfl_xor_sync(0xffffffffu, q, o);
        float rstd = rsqrtf(q * (1.0f / 128.0f) + 1e-5f);
        float w[8];
#pragma unroll
        for (int j = 0; j < 8; j++) w[j] = d[j] * rstd * gg[j] + lb[j];
        *(float4*)&g_h[r * kH + tx * 8]     = make_float4(w[0], w[1], w[2], w[3]);
        *(float4*)&g_h[r * kH + tx * 8 + 4] = make_float4(w[4], w[5], w[6], w[7]);
        if (!LAST) {
            int rl = ty * 4 + i;
#pragma unroll
            for (int j = 0; j < 8; j++) As[rl * kH + tx * 8 + j] = w[j];
        }
    }

    if (!LAST) {
        // Wnext -> Bs, then stage3: hs = h @ Wnext (fp16 out)
        const float4* WN4 = (const float4*)Wnext;
#pragma unroll
        for (int i = 0; i < 16; i++) Bs4[tid + i * 256] = WN4[tid + i * 256];
        __syncthreads();

#pragma unroll
        for (int i = 0; i < 4; i++)
#pragma unroll
            for (int j = 0; j < 8; j++) acc[i][j] = 0.0f;
#pragma unroll 8
        for (int k = 0; k < kH; k++) {
            float av[4];
#pragma unroll
            for (int i = 0; i < 4; i++) av[i] = As[(ty * 4 + i) * kH + k];
            float4 b0v = *(const float4*)&Bs[k * kH + tx * 8];
            float4 b1v = *(const float4*)&Bs[k * kH + tx * 8 + 4];
            float bv[8] = {b0v.x, b0v.y, b0v.z, b0v.w, b1v.x, b1v.y, b1v.z, b1v.w};
#pragma unroll
            for (int i = 0; i < 4; i++)
#pragma unroll
                for (int j = 0; j < 8; j++) acc[i][j] += av[i] * bv[j];
        }
#pragma unroll
        for (int i = 0; i < 4; i++) {
            int r = m0 + ty * 4 + i;
            __half2 p0 = __floats2half2_rn(acc[i][0], acc[i][1]);
            __half2 p1 = __floats2half2_rn(acc[i][2], acc[i][3]);
            __half2 p2 = __floats2half2_rn(acc[i][4], acc[i][5]);
            __half2 p3 = __floats2half2_rn(acc[i][6], acc[i][7]);
            uint4 u;
            u.x = *reinterpret_cast<unsigned*>(&p0);
            u.y = *reinterpret_cast<unsigned*>(&p1);
            u.z = *reinterpret_cast<unsigned*>(&p2);
            u.w = *reinterpret_cast<unsigned*>(&p3);
            *reinterpret_cast<uint4*>(&g_hsh[r * kH + tx * 8]) = u;
        }
    }
}

// ---------------- readout ----------------
__global__ void readout_kernel(float* __restrict__ out,
                               const float* __restrict__ w1, const float* __restrict__ b1,
                               const float* __restrict__ w2, const float* __restrict__ b2) {
    __shared__ float s[kH];
    __shared__ float red[2];
    int n   = blockIdx.x;
    int tid = threadIdx.x;
    s[tid] = silu(g_h[n * kH + tid]);
    __syncthreads();
    float e = 0.0f;
    if (tid < 64) {
        float x = b1[tid];
#pragma unroll 8
        for (int k = 0; k < kH; k++) x += s[k] * w1[k * 64 + tid];
        e = silu(x) * w2[tid];
    }
#pragma unroll
    for (int off = 16; off; off >>= 1) e += __shfl_down_sync(0xffffffffu, e, off);
    if (tid == 0)  red[0] = e;
    if (tid == 32) red[1] = e;
    __syncthreads();
    if (tid == 0) atomicAdd(&out[n >> 7], red[0] + red[1] + b2[0]);
}

// ---------------- launcher ----------------
extern "C" void kernel_launch(void* const* d_in, const int* in_sizes, int n_in,
                              void* d_out, int out_size) {
    (void)in_sizes; (void)n_in; (void)out_size;
    const int*   Z        = (const int*)  d_in[0];
    const float* pos      = (const float*)d_in[1];
    const int*   ei       = (const int*)  d_in[2];
    const float* embed_w  = (const float*)d_in[3];
    const float* edge_w1  = (const float*)d_in[4];
    const float* edge_b1  = (const float*)d_in[5];
    const float* edge_w2  = (const float*)d_in[6];
    const float* edge_b2  = (const float*)d_in[7];
    const float* lin_in_w = (const float*)d_in[8];
    const float* node_w1  = (const float*)d_in[9];
    const float* node_b1  = (const float*)d_in[10];
    const float* node_w2  = (const float*)d_in[11];
    const float* node_b2  = (const float*)d_in[12];
    const float* ln_g     = (const float*)d_in[13];
    const float* ln_b     = (const float*)d_in[14];
    const float* ro_w1    = (const float*)d_in[15];
    const float* ro_b1    = (const float*)d_in[16];
    const float* ro_w2    = (const float*)d_in[17];
    const float* ro_b2    = (const float*)d_in[18];
    float* out = (float*)d_out;

    float *ph;
    __half *phs;
    cudaGetSymbolAddress((void**)&ph,  g_h);
    cudaGetSymbolAddress((void**)&phs, g_hsh);

    const int GEMM_SMEM = (64 * kH + kH * kH) * (int)sizeof(float);                   // 96 KB
    const int TAB_SMEM  = (kNRBF * kH + kH * kH + 2 * kH + 2 * kNRBF) * (int)sizeof(float);
    cudaFuncSetAttribute(gemm_h_kernel,        cudaFuncAttributeMaxDynamicSharedMemorySize, GEMM_SMEM);
    cudaFuncSetAttribute(node_fused_kernel<0>, cudaFuncAttributeMaxDynamicSharedMemorySize, GEMM_SMEM);
    cudaFuncSetAttribute(node_fused_kernel<1>, cudaFuncAttributeMaxDynamicSharedMemorySize, GEMM_SMEM);
    cudaFuncSetAttribute(table_kernel,         cudaFuncAttributeMaxDynamicSharedMemorySize, TAB_SMEM);

    // ---- prep: embedding (+deg zero), bucket scatter, filter tables ----
    embed_kernel<<<kBN, kH>>>(Z, embed_w);
    scatter_kernel<<<kE / 512, 256>>>(ei, pos);
    table_kernel<<<dim3(kNGRID / 32, kNBLK), 256, TAB_SMEM>>>(edge_w1, edge_b1, edge_w2, edge_b2);
    gemm_h_kernel<<<kBN / 64, 256, GEMM_SMEM>>>(ph, lin_in_w, phs);   // hs for block 0

    // ---- 4 interaction blocks ----
    for (int b = 0; b < kNBLK; b++) {
        agg_kernel<<<kBN / 4, 128>>>(b);
        if (b < kNBLK - 1) {
            node_fused_kernel<0><<<kBN / 64, 256, GEMM_SMEM>>>(
                node_w1 + b * kH * kH, node_b1 + b * kH,
                node_w2 + b * kH * kH, node_b2 + b * kH,
                ln_g + b * kH, ln_b + b * kH,
                lin_in_w + (b + 1) * kH * kH);
        } else {
            node_fused_kernel<1><<<kBN / 64, 256, GEMM_SMEM>>>(
                node_w1 + b * kH * kH, node_b1 + b * kH,
                node_w2 + b * kH * kH, node_b2 + b * kH,
                ln_g + b * kH, ln_b + b * kH, nullptr);
        }
    }

    // ---- readout ----
    zero_out_kernel<<<1, 64>>>(out);
    readout_kernel<<<kBN, kH>>>(out, ro_w1, ro_b1, ro_w2, ro_b2);
}

// round 6
// speedup vs baseline: 1.3883x; 1.0897x over previous
#include <cuda_runtime.h>
#include <cuda_fp16.h>
#include <math.h>

// ---------------- problem constants ----------------
#define kB     64
#define kBN    8192        // B*N nodes
#define kE     262144      // edges
#define kH     128
#define kNRBF  64
#define kNBLK  4
#define kNGRID 512         // filter table resolution
#define kCAP   128         // max edges per node bucket (lambda=32)
#define kRCUT  6.0f
#define kGAMMA (10.0f / 36.0f)

// ---------------- device scratch ----------------
__device__ float  g_h  [kBN * kH];
__device__ __half g_hsh[kBN * kH];               // h @ lin_in, fp16
__device__ float  g_agg[kBN * kH];
__device__ __half g_tabh[kNBLK * kNGRID * kH];   // w(d) table, fp16
__device__ int    g_deg[kBN];

struct __align__(8) SEdge { int s; float t; };
__device__ SEdge g_se[kBN * kCAP];   // bucketed edges per dst node

__device__ __forceinline__ float silu(float x) { return x / (1.0f + expf(-x)); }

// load 128x128 fp32 weight matrix from global into fp16 smem (uint2 per float4)
__device__ __forceinline__ void load_w_half(const float* __restrict__ W,
                                            __half* __restrict__ Bsh, int tid) {
    const float4* W4 = (const float4*)W;
    uint2* B2 = (uint2*)Bsh;
#pragma unroll
    for (int i = 0; i < 16; i++) {
        float4 w = W4[tid + i * 256];
        __half2 a = __floats2half2_rn(w.x, w.y);
        __half2 b = __floats2half2_rn(w.z, w.w);
        uint2 u;
        u.x = *reinterpret_cast<unsigned*>(&a);
        u.y = *reinterpret_cast<unsigned*>(&b);
        B2[tid + i * 256] = u;
    }
}

// read 8 fp16 weights at [k][tx*8..] and widen to fp32
__device__ __forceinline__ void read_w8(const __half* __restrict__ Bsh, int k, int tx,
                                        float bv[8]) {
    uint4 bq = *(const uint4*)&Bsh[k * kH + tx * 8];
    float2 f0 = __half22float2(*reinterpret_cast<__half2*>(&bq.x));
    float2 f1 = __half22float2(*reinterpret_cast<__half2*>(&bq.y));
    float2 f2 = __half22float2(*reinterpret_cast<__half2*>(&bq.z));
    float2 f3 = __half22float2(*reinterpret_cast<__half2*>(&bq.w));
    bv[0] = f0.x; bv[1] = f0.y; bv[2] = f1.x; bv[3] = f1.y;
    bv[4] = f2.x; bv[5] = f2.y; bv[6] = f3.x; bv[7] = f3.y;
}

// ---------------- prep kernels ----------------
__global__ void zero_out_kernel(float* out) {
    if (threadIdx.x < kB) out[threadIdx.x] = 0.0f;
}

__global__ void embed_kernel(const int* __restrict__ Z, const float* __restrict__ ew) {
    int n = blockIdx.x;
    int c = threadIdx.x;
    g_h[n * kH + c] = ew[Z[n] * kH + c];
    if (c == 0) g_deg[n] = 0;
}

// direct bucket scatter: 2 edges per thread, batched loads for ILP
__global__ void scatter_kernel(const int* __restrict__ ei, const float* __restrict__ pos) {
    int t2 = blockIdx.x * blockDim.x + threadIdx.x;
    int2 sp = *(const int2*)(ei + t2 * 2);        // src pair
    int2 dp = *(const int2*)(ei + kE + t2 * 2);   // dst pair
    float s0x = pos[sp.x * 3 + 0], s0y = pos[sp.x * 3 + 1], s0z = pos[sp.x * 3 + 2];
    float d0x = pos[dp.x * 3 + 0], d0y = pos[dp.x * 3 + 1], d0z = pos[dp.x * 3 + 2];
    float s1x = pos[sp.y * 3 + 0], s1y = pos[sp.y * 3 + 1], s1z = pos[sp.y * 3 + 2];
    float d1x = pos[dp.y * 3 + 0], d1y = pos[dp.y * 3 + 1], d1z = pos[dp.y * 3 + 2];
    float ax = s0x - d0x, ay = s0y - d0y, az = s0z - d0z;
    float bx = s1x - d1x, by = s1y - d1y, bz = s1z - d1z;
    float r0 = fminf(sqrtf(ax * ax + ay * ay + az * az), kRCUT);
    float r1 = fminf(sqrtf(bx * bx + by * by + bz * bz), kRCUT);
    const float sc = (float)(kNGRID - 1) / kRCUT;
    int p0 = atomicAdd(&g_deg[dp.x], 1);
    int p1 = atomicAdd(&g_deg[dp.y], 1);
    SEdge e0; e0.s = sp.x; e0.t = r0 * sc;
    SEdge e1; e1.s = sp.y; e1.t = r1 * sc;
    if (p0 < kCAP) g_se[dp.x * kCAP + p0] = e0;
    if (p1 < kCAP) g_se[dp.y * kCAP + p1] = e1;
}

// ---------------- edge-filter lookup table (fp16) ----------------
__global__ void __launch_bounds__(256) table_kernel(
        const float* __restrict__ w1, const float* __restrict__ b1,
        const float* __restrict__ w2, const float* __restrict__ b2) {
    extern __shared__ float sm[];
    float* sW1  = sm;                       // 64*128
    float* sW2  = sW1 + kNRBF * kH;         // 128*128
    float* sh   = sW2 + kH * kH;            // 2*128
    float* srbf = sh + 2 * kH;              // 2*64
    int blk  = blockIdx.y;
    int tid  = threadIdx.x;
    int c    = tid & 127;
    int half = tid >> 7;
    const float* W1 = w1 + blk * kNRBF * kH;
    const float* W2 = w2 + blk * kH * kH;
    float bb1 = b1[blk * kH + c];
    float bb2 = b2[blk * kH + c];
    for (int i = tid; i < kNRBF * kH; i += 256) sW1[i] = W1[i];
    for (int i = tid; i < kH * kH;   i += 256) sW2[i] = W2[i];
    __syncthreads();

    int g0 = blockIdx.x * 32;
    for (int it = 0; it < 16; it++) {
        int g = g0 + it * 2 + half;
        float dd = kRCUT * (float)g / (float)(kNGRID - 1);
        if (c < kNRBF) {
            float ck = kRCUT * (float)c / (float)(kNRBF - 1);
            float u  = dd - ck;
            srbf[half * kNRBF + c] = expf(-kGAMMA * u * u);
        }
        __syncthreads();
        float a0 = 0, a1 = 0, a2 = 0, a3 = 0;
        const float* rb = srbf + half * kNRBF;
#pragma unroll
        for (int k = 0; k < kNRBF; k += 4) {
            a0 += rb[k + 0] * sW1[(k + 0) * kH + c];
            a1 += rb[k + 1] * sW1[(k + 1) * kH + c];
            a2 += rb[k + 2] * sW1[(k + 2) * kH + c];
            a3 += rb[k + 3] * sW1[(k + 3) * kH + c];
        }
        sh[half * kH + c] = silu(a0 + a1 + a2 + a3 + bb1);
        __syncthreads();
        float o0 = 0, o1 = 0, o2 = 0, o3 = 0;
        const float* hh = sh + half * kH;
#pragma unroll
        for (int j = 0; j < kH; j += 4) {
            o0 += hh[j + 0] * sW2[(j + 0) * kH + c];
            o1 += hh[j + 1] * sW2[(j + 1) * kH + c];
            o2 += hh[j + 2] * sW2[(j + 2) * kH + c];
            o3 += hh[j + 3] * sW2[(j + 3) * kH + c];
        }
        g_tabh[(blk * kNGRID + g) * kH + c] = __float2half_rn(o0 + o1 + o2 + o3 + bb2);
        __syncthreads();
    }
}

// ---------------- initial GEMM hs = h @ lin_in[0], fp16 out ----------------
// dyn smem: As fp32 32KB + Bs fp16 32KB = 64KB -> 3 CTAs/SM
__global__ void __launch_bounds__(256) gemm_h_kernel(const float* __restrict__ A,
                                                     const float* __restrict__ W,
                                                     __half* __restrict__ C) {
    extern __shared__ float sm[];
    float*  As  = sm;                       // 64*128 fp32
    __half* Bsh = (__half*)(sm + 64 * kH);  // 128*128 fp16
    int tid = threadIdx.x;
    int m0  = blockIdx.x * 64;

    const float4* A4  = (const float4*)(A + m0 * kH);
    float4*       As4 = (float4*)As;
#pragma unroll
    for (int i = 0; i < 8; i++) As4[tid + i * 256] = A4[tid + i * 256];
    load_w_half(W, Bsh, tid);
    __syncthreads();

    int ty = tid >> 4;
    int tx = tid & 15;
    float acc[4][8];
#pragma unroll
    for (int i = 0; i < 4; i++)
#pragma unroll
        for (int j = 0; j < 8; j++) acc[i][j] = 0.0f;

#pragma unroll 8
    for (int k = 0; k < kH; k++) {
        float av[4];
#pragma unroll
        for (int i = 0; i < 4; i++) av[i] = As[(ty * 4 + i) * kH + k];
        float bv[8];
        read_w8(Bsh, k, tx, bv);
#pragma unroll
        for (int i = 0; i < 4; i++)
#pragma unroll
            for (int j = 0; j < 8; j++) acc[i][j] += av[i] * bv[j];
    }

#pragma unroll
    for (int i = 0; i < 4; i++) {
        int r = m0 + ty * 4 + i;
        __half2 p0 = __floats2half2_rn(acc[i][0], acc[i][1]);
        __half2 p1 = __floats2half2_rn(acc[i][2], acc[i][3]);
        __half2 p2 = __floats2half2_rn(acc[i][4], acc[i][5]);
        __half2 p3 = __floats2half2_rn(acc[i][6], acc[i][7]);
        uint4 u;
        u.x = *reinterpret_cast<unsigned*>(&p0);
        u.y = *reinterpret_cast<unsigned*>(&p1);
        u.z = *reinterpret_cast<unsigned*>(&p2);
        u.w = *reinterpret_cast<unsigned*>(&p3);
        *reinterpret_cast<uint4*>(&C[r * kH + tx * 8]) = u;
    }
}

// ---------------- edge aggregation: warp/node, fp16 table + fp16 hs ----------------
__global__ void __launch_bounds__(128) agg_kernel(int blk) {
    int warp = threadIdx.x >> 5;
    int lane = threadIdx.x & 31;
    int n    = blockIdx.x * 4 + warp;
    const uint2* tab = (const uint2*)(g_tabh + blk * kNGRID * kH);
    const uint2* hs  = (const uint2*)g_hsh;
    int len  = g_deg[n];
    if (len > kCAP) len = kCAP;
    const SEdge* row = g_se + n * kCAP;
    float4 acc = make_float4(0.f, 0.f, 0.f, 0.f);
    for (int p = 0; p < len; p++) {
        SEdge e = row[p];
        float t = e.t;
        int   gdx = (int)t;
        if (gdx > kNGRID - 2) gdx = kNGRID - 2;
        float f = t - (float)gdx;
        uint2 u0 = tab[gdx * 32 + lane];
        uint2 u1 = tab[(gdx + 1) * 32 + lane];
        uint2 uh = hs[e.s * 32 + lane];
        float2 w0a = __half22float2(*reinterpret_cast<__half2*>(&u0.x));
        float2 w0b = __half22float2(*reinterpret_cast<__half2*>(&u0.y));
        float2 w1a = __half22float2(*reinterpret_cast<__half2*>(&u1.x));
        float2 w1b = __half22float2(*reinterpret_cast<__half2*>(&u1.y));
        float2 hva = __half22float2(*reinterpret_cast<__half2*>(&uh.x));
        float2 hvb = __half22float2(*reinterpret_cast<__half2*>(&uh.y));
        acc.x += (w0a.x + (w1a.x - w0a.x) * f) * hva.x;
        acc.y += (w0a.y + (w1a.y - w0a.y) * f) * hva.y;
        acc.z += (w0b.x + (w1b.x - w0b.x) * f) * hvb.x;
        acc.w += (w0b.y + (w1b.y - w0b.y) * f) * hvb.y;
    }
    ((float4*)g_agg)[n * 32 + lane] = acc;
}

// ---------------- fused node MLP + residual + LayerNorm + next lin_in ----------------
// stage1: t1 = silu(agg@W1+b1) (smem); stage2: h = LN(h + t1@W2+b2);
// stage3 (if !LAST): hs = h @ Wnext -> fp16
template <int LAST>
__global__ void __launch_bounds__(256) node_fused_kernel(
        const float* __restrict__ W1, const float* __restrict__ b1,
        const float* __restrict__ W2, const float* __restrict__ b2,
        const float* __restrict__ lng, const float* __restrict__ lnb,
        const float* __restrict__ Wnext) {
    extern __shared__ float sm[];
    float*  As  = sm;                       // 64*128 fp32 (agg -> t1 -> h)
    __half* Bsh = (__half*)(sm + 64 * kH);  // 128*128 fp16 (W1 -> W2 -> Wnext)
    int tid = threadIdx.x;
    int m0  = blockIdx.x * 64;
    int ty  = tid >> 4;
    int tx  = tid & 15;

    const float4* A4  = (const float4*)(g_agg + m0 * kH);
    float4*       As4 = (float4*)As;
#pragma unroll
    for (int i = 0; i < 8; i++) As4[tid + i * 256] = A4[tid + i * 256];
    load_w_half(W1, Bsh, tid);
    __syncthreads();

    float acc[4][8];
#pragma unroll
    for (int i = 0; i < 4; i++)
#pragma unroll
        for (int j = 0; j < 8; j++) acc[i][j] = 0.0f;
#pragma unroll 8
    for (int k = 0; k < kH; k++) {
        float av[4];
#pragma unroll
        for (int i = 0; i < 4; i++) av[i] = As[(ty * 4 + i) * kH + k];
        float bv[8];
        read_w8(Bsh, k, tx, bv);
#pragma unroll
        for (int i = 0; i < 4; i++)
#pragma unroll
            for (int j = 0; j < 8; j++) acc[i][j] += av[i] * bv[j];
    }
    __syncthreads();

    // t1 = silu(acc + b1) -> As ; W2 -> Bsh
    {
        float4 bb0 = *(const float4*)&b1[tx * 8];
        float4 bb1 = *(const float4*)&b1[tx * 8 + 4];
        float bb[8] = {bb0.x, bb0.y, bb0.z, bb0.w, bb1.x, bb1.y, bb1.z, bb1.w};
#pragma unroll
        for (int i = 0; i < 4; i++) {
            int r = ty * 4 + i;
#pragma unroll
            for (int j = 0; j < 8; j++)
                As[r * kH + tx * 8 + j] = silu(acc[i][j] + bb[j]);
        }
        load_w_half(W2, Bsh, tid);
    }
    __syncthreads();

#pragma unroll
    for (int i = 0; i < 4; i++)
#pragma unroll
        for (int j = 0; j < 8; j++) acc[i][j] = 0.0f;
#pragma unroll 8
    for (int k = 0; k < kH; k++) {
        float av[4];
#pragma unroll
        for (int i = 0; i < 4; i++) av[i] = As[(ty * 4 + i) * kH + k];
        float bv[8];
        read_w8(Bsh, k, tx, bv);
#pragma unroll
        for (int i = 0; i < 4; i++)
#pragma unroll
            for (int j = 0; j < 8; j++) acc[i][j] += av[i] * bv[j];
    }
    __syncthreads();   // stage-2 reads of As/Bsh done; safe to overwrite

    // epilogue: + b2 + residual, LayerNorm across 16 tx-threads per row
    float4 bb0 = *(const float4*)&b2[tx * 8];
    float4 bb1 = *(const float4*)&b2[tx * 8 + 4];
    float bb[8] = {bb0.x, bb0.y, bb0.z, bb0.w, bb1.x, bb1.y, bb1.z, bb1.w};
    float4 gg0 = *(const float4*)&lng[tx * 8];
    float4 gg1 = *(const float4*)&lng[tx * 8 + 4];
    float gg[8] = {gg0.x, gg0.y, gg0.z, gg0.w, gg1.x, gg1.y, gg1.z, gg1.w};
    float4 lb0 = *(const float4*)&lnb[tx * 8];
    float4 lb1 = *(const float4*)&lnb[tx * 8 + 4];
    float lb[8] = {lb0.x, lb0.y, lb0.z, lb0.w, lb1.x, lb1.y, lb1.z, lb1.w};

#pragma unroll
    for (int i = 0; i < 4; i++) {
        int r = m0 + ty * 4 + i;
        float4 h0 = *(const float4*)&g_h[r * kH + tx * 8];
        float4 h1 = *(const float4*)&g_h[r * kH + tx * 8 + 4];
        float hv[8] = {h0.x, h0.y, h0.z, h0.w, h1.x, h1.y, h1.z, h1.w};
        float v[8];
        float s = 0.0f;
#pragma unroll
        for (int j = 0; j < 8; j++) { v[j] = acc[i][j] + bb[j] + hv[j]; s += v[j]; }
#pragma unroll
        for (int o = 1; o < 16; o <<= 1) s += __shfl_xor_sync(0xffffffffu, s, o);
        float mu = s * (1.0f / 128.0f);
        float q = 0.0f;
        float d[8];
#pragma unroll
        for (int j = 0; j < 8; j++) { d[j] = v[j] - mu; q += d[j] * d[j]; }
#pragma unroll
        for (int o = 1; o < 16; o <<= 1) q += __shfl_xor_sync(0xffffffffu, q, o);
        float rstd = rsqrtf(q * (1.0f / 128.0f) + 1e-5f);
        float w[8];
#pragma unroll
        for (int j = 0; j < 8; j++) w[j] = d[j] * rstd * gg[j] + lb[j];
        *(float4*)&g_h[r * kH + tx * 8]     = make_float4(w[0], w[1], w[2], w[3]);
        *(float4*)&g_h[r * kH + tx * 8 + 4] = make_float4(w[4], w[5], w[6], w[7]);
        if (!LAST) {
            int rl = ty * 4 + i;
#pragma unroll
            for (int j = 0; j < 8; j++) As[rl * kH + tx * 8 + j] = w[j];
        }
    }

    if (!LAST) {
        load_w_half(Wnext, Bsh, tid);
        __syncthreads();

#pragma unroll
        for (int i = 0; i < 4; i++)
#pragma unroll
            for (int j = 0; j < 8; j++) acc[i][j] = 0.0f;
#pragma unroll 8
        for (int k = 0; k < kH; k++) {
            float av[4];
#pragma unroll
            for (int i = 0; i < 4; i++) av[i] = As[(ty * 4 + i) * kH + k];
            float bv[8];
            read_w8(Bsh, k, tx, bv);
#pragma unroll
            for (int i = 0; i < 4; i++)
#pragma unroll
                for (int j = 0; j < 8; j++) acc[i][j] += av[i] * bv[j];
        }
#pragma unroll
        for (int i = 0; i < 4; i++) {
            int r = m0 + ty * 4 + i;
            __half2 p0 = __floats2half2_rn(acc[i][0], acc[i][1]);
            __half2 p1 = __floats2half2_rn(acc[i][2], acc[i][3]);
            __half2 p2 = __floats2half2_rn(acc[i][4], acc[i][5]);
            __half2 p3 = __floats2half2_rn(acc[i][6], acc[i][7]);
            uint4 u;
            u.x = *reinterpret_cast<unsigned*>(&p0);
            u.y = *reinterpret_cast<unsigned*>(&p1);
            u.z = *reinterpret_cast<unsigned*>(&p2);
            u.w = *reinterpret_cast<unsigned*>(&p3);
            *reinterpret_cast<uint4*>(&g_hsh[r * kH + tx * 8]) = u;
        }
    }
}

// ---------------- readout ----------------
__global__ void readout_kernel(float* __restrict__ out,
                               const float* __restrict__ w1, const float* __restrict__ b1,
                               const float* __restrict__ w2, const float* __restrict__ b2) {
    __shared__ float s[kH];
    __shared__ float red[2];
    int n   = blockIdx.x;
    int tid = threadIdx.x;
    s[tid] = silu(g_h[n * kH + tid]);
    __syncthreads();
    float e = 0.0f;
    if (tid < 64) {
        float x = b1[tid];
#pragma unroll 8
        for (int k = 0; k < kH; k++) x += s[k] * w1[k * 64 + tid];
        e = silu(x) * w2[tid];
    }
#pragma unroll
    for (int off = 16; off; off >>= 1) e += __shfl_down_sync(0xffffffffu, e, off);
    if (tid == 0)  red[0] = e;
    if (tid == 32) red[1] = e;
    __syncthreads();
    if (tid == 0) atomicAdd(&out[n >> 7], red[0] + red[1] + b2[0]);
}

// ---------------- launcher ----------------
extern "C" void kernel_launch(void* const* d_in, const int* in_sizes, int n_in,
                              void* d_out, int out_size) {
    (void)in_sizes; (void)n_in; (void)out_size;
    const int*   Z        = (const int*)  d_in[0];
    const float* pos      = (const float*)d_in[1];
    const int*   ei       = (const int*)  d_in[2];
    const float* embed_w  = (const float*)d_in[3];
    const float* edge_w1  = (const float*)d_in[4];
    const float* edge_b1  = (const float*)d_in[5];
    const float* edge_w2  = (const float*)d_in[6];
    const float* edge_b2  = (const float*)d_in[7];
    const float* lin_in_w = (const float*)d_in[8];
    const float* node_w1  = (const float*)d_in[9];
    const float* node_b1  = (const float*)d_in[10];
    const float* node_w2  = (const float*)d_in[11];
    const float* node_b2  = (const float*)d_in[12];
    const float* ln_g     = (const float*)d_in[13];
    const float* ln_b     = (const float*)d_in[14];
    const float* ro_w1    = (const float*)d_in[15];
    const float* ro_b1    = (const float*)d_in[16];
    const float* ro_w2    = (const float*)d_in[17];
    const float* ro_b2    = (const float*)d_in[18];
    float* out = (float*)d_out;

    float *ph;
    __half *phs;
    cudaGetSymbolAddress((void**)&ph,  g_h);
    cudaGetSymbolAddress((void**)&phs, g_hsh);

    const int GEMM_SMEM = 64 * kH * (int)sizeof(float) + kH * kH * (int)sizeof(__half); // 64 KB
    const int TAB_SMEM  = (kNRBF * kH + kH * kH + 2 * kH + 2 * kNRBF) * (int)sizeof(float);
    cudaFuncSetAttribute(gemm_h_kernel,        cudaFuncAttributeMaxDynamicSharedMemorySize, GEMM_SMEM);
    cudaFuncSetAttribute(node_fused_kernel<0>, cudaFuncAttributeMaxDynamicSharedMemorySize, GEMM_SMEM);
    cudaFuncSetAttribute(node_fused_kernel<1>, cudaFuncAttributeMaxDynamicSharedMemorySize, GEMM_SMEM);
    cudaFuncSetAttribute(table_kernel,         cudaFuncAttributeMaxDynamicSharedMemorySize, TAB_SMEM);

    // ---- prep: embedding (+deg zero), bucket scatter, filter tables ----
    embed_kernel<<<kBN, kH>>>(Z, embed_w);
    scatter_kernel<<<kE / 512, 256>>>(ei, pos);
    table_kernel<<<dim3(kNGRID / 32, kNBLK), 256, TAB_SMEM>>>(edge_w1, edge_b1, edge_w2, edge_b2);
    gemm_h_kernel<<<kBN / 64, 256, GEMM_SMEM>>>(ph, lin_in_w, phs);   // hs for block 0

    // ---- 4 interaction blocks ----
    for (int b = 0; b < kNBLK; b++) {
        agg_kernel<<<kBN / 4, 128>>>(b);
        if (b < kNBLK - 1) {
            node_fused_kernel<0><<<kBN / 64, 256, GEMM_SMEM>>>(
                node_w1 + b * kH * kH, node_b1 + b * kH,
                node_w2 + b * kH * kH, node_b2 + b * kH,
                ln_g + b * kH, ln_b + b * kH,
                lin_in_w + (b + 1) * kH * kH);
        } else {
            node_fused_kernel<1><<<kBN / 64, 256, GEMM_SMEM>>>(
                node_w1 + b * kH * kH, node_b1 + b * kH,
                node_w2 + b * kH * kH, node_b2 + b * kH,
                ln_g + b * kH, ln_b + b * kH, nullptr);
        }
    }

    // ---- readout ----
    zero_out_kernel<<<1, 64>>>(out);
    readout_kernel<<<kBN, kH>>>(out, ro_w1, ro_b1, ro_w2, ro_b2);
}